// round 13
// baseline (speedup 1.0000x reference)
#include <cuda_runtime.h>
#include <mma.h>
#include <cstdint>

using namespace nvcuda;

#define NN 100000
#define NNP 100096              // 782 * 128, padded for unguarded wmma stores
#define EE 1600000
#define ET (EE + NN)            // 1,700,000 edges incl self loops

#define NB 256                  // scan blocks
#define CB 391                  // ceil(NN/NB)
#define TS 2                    // elems per thread in scan block

// ---------------- scratch (device globals; no runtime alloc) ----------------
__device__ __align__(16) float  g_xl1[NNP * 128];
__device__ __align__(16) float  g_xr1[NNP * 128];
__device__ __align__(16) float  g_h1 [NN * 128];   // normalized conv1 output (pre-BN)
__device__ __align__(16) float  g_e1 [ET * 4];     // exp(score), ORIGINAL edge order
__device__ __align__(16) double g_bnsum[128];
__device__ __align__(16) double g_bnsq [128];
__device__ __align__(16) float  g_scale[128];
__device__ __align__(16) float  g_shift[128];      // includes b1 & beta & mean folded
__device__ __align__(16) float  g_xl2[NN * 32];
__device__ __align__(16) float  g_xr2[NN * 32];
__device__ __align__(16) float  g_h2 [NN * 32];    // normalized conv2 output
// CSR edge structure (dst-sorted)
__device__ int g_cnt [NN];
__device__ int g_rs  [NN + 1];
__device__ int g_bsum[NB];
__device__ int g_esrc[ET];
__device__ int g_eid [ET];
__device__ int g_ei64;

__device__ __forceinline__ float lrelu(float v, float s) { return v > 0.f ? v : s * v; }

__device__ __forceinline__ void edge_sd(const void* __restrict__ ei, int use64,
                                        int e, int& s, int& d) {
    if (e < EE) {
        if (use64) {
            const long long* p = (const long long*)ei;
            s = (int)p[e]; d = (int)p[EE + e];
        } else {
            const int* p = (const int*)ei;
            s = p[e]; d = p[EE + e];
        }
    } else { s = e - EE; d = e - EE; }
}

__device__ __forceinline__ int edge_d(const void* __restrict__ ei, int use64, int e) {
    if (e < EE) {
        if (use64) return (int)((const long long*)ei)[EE + e];
        return ((const int*)ei)[EE + e];
    }
    return e - EE;
}

// ---------------- dtype probe ----------------
__global__ void k_detect(const void* __restrict__ ei) {
    if (threadIdx.x == 0 && blockIdx.x == 0) {
        const long long* p = (const long long*)ei;
        int ok = 1;
        #pragma unroll
        for (int i = 0; i < 8; i++) {
            long long v = p[i];
            if (v < 0 || v >= NN) ok = 0;
        }
        g_ei64 = ok;
    }
}

// ---------------- CSR build ----------------
__global__ void k_zero_cnt() {
    int i = blockIdx.x * blockDim.x + threadIdx.x;
    int st = gridDim.x * blockDim.x;
    for (; i < NN; i += st) g_cnt[i] = 0;
}

__global__ void k_hist(const void* __restrict__ ei) {
    int i = blockIdx.x * blockDim.x + threadIdx.x;
    int st = gridDim.x * blockDim.x;
    int use64 = g_ei64;
    for (; i < ET; i += st) atomicAdd(&g_cnt[edge_d(ei, use64, i)], 1);
}

__global__ void k_scanA() {
    int b = blockIdx.x, t = threadIdx.x;
    int lo = b * CB + t * TS;
    int hi = min(b * CB + CB, NN);
    int s = 0;
    #pragma unroll
    for (int k = 0; k < TS; k++) {
        int i = lo + k;
        if (i < hi) s += g_cnt[i];
    }
    __shared__ int sh[256];
    sh[t] = s; __syncthreads();
    for (int off = 128; off; off >>= 1) {
        if (t < off) sh[t] += sh[t + off];
        __syncthreads();
    }
    if (t == 0) g_bsum[b] = sh[0];
}

__global__ void k_scanB() {
    __shared__ int sh[NB];
    int t = threadIdx.x;
    sh[t] = g_bsum[t]; __syncthreads();
    for (int off = 1; off < NB; off <<= 1) {
        int v = (t >= off) ? sh[t - off] : 0;
        __syncthreads();
        sh[t] += v;
        __syncthreads();
    }
    g_bsum[t] = t ? sh[t - 1] : 0;
}

__global__ void k_scanC() {
    int b = blockIdx.x, t = threadIdx.x;
    int lo = b * CB + t * TS;
    int hi = min(b * CB + CB, NN);
    int s = 0;
    #pragma unroll
    for (int k = 0; k < TS; k++) {
        int i = lo + k;
        if (i < hi) s += g_cnt[i];
    }
    __shared__ int sh[256];
    sh[t] = s; __syncthreads();
    for (int off = 1; off < 256; off <<= 1) {
        int v = (t >= off) ? sh[t - off] : 0;
        __syncthreads();
        sh[t] += v;
        __syncthreads();
    }
    int run = g_bsum[b] + (t ? sh[t - 1] : 0);
    #pragma unroll
    for (int k = 0; k < TS; k++) {
        int i = lo + k;
        if (i < hi) {
            int c = g_cnt[i];
            g_rs[i] = run;
            run += c;
            g_cnt[i] = 0;
        }
    }
    if (b == 0 && t == 0) g_rs[NN] = ET;
}

__global__ void k_scatter(const void* __restrict__ ei) {
    int i = blockIdx.x * blockDim.x + threadIdx.x;
    int st = gridDim.x * blockDim.x;
    int use64 = g_ei64;
    for (; i < ET; i += st) {
        int s, d; edge_sd(ei, use64, i, s, d);
        int pos = g_rs[d] + atomicAdd(&g_cnt[d], 1);
        g_esrc[pos] = s;
        g_eid[pos]  = i;
    }
}

// ---------------- GEMM1 (TF32 tensor cores): block 128(M)x128(N-half), 8 warps -------
// blockIdx.y = 0 -> Wl -> g_xl1, 1 -> Wr -> g_xr1
__global__ void k_gemm1_tf32(const float* __restrict__ x,
                             const float* __restrict__ Wl, const float* __restrict__ Wr) {
    extern __shared__ float sm[];
    float* xs = sm;               // 128 x 128 (M x K)
    float* ws = sm + 128 * 128;   // 128 x 128 (K x N)
    int tid = threadIdx.x;
    int m0  = blockIdx.x * 128;
    const float* W = blockIdx.y ? Wr : Wl;
    float* outp = blockIdx.y ? g_xr1 : g_xl1;

    for (int idx = tid * 4; idx < 128 * 128; idx += 256 * 4)
        *(float4*)&ws[idx] = *(const float4*)&W[idx];
    for (int idx = tid * 4; idx < 128 * 128; idx += 256 * 4) {
        int r = idx >> 7, c = idx & 127;
        int row = m0 + r;
        float4 v = make_float4(0.f, 0.f, 0.f, 0.f);
        if (row < NN) v = *(const float4*)&x[row * 128 + c];
        *(float4*)&xs[idx] = v;
    }
    __syncthreads();

    int wid = tid >> 5;
    int wm = wid & 1, wn = wid >> 1;   // warp tile: rows wm*64..+64, cols wn*32..+32

    wmma::fragment<wmma::accumulator, 16, 16, 8, float> acc[4][2];
    #pragma unroll
    for (int i = 0; i < 4; i++)
        #pragma unroll
        for (int j = 0; j < 2; j++) wmma::fill_fragment(acc[i][j], 0.f);

    #pragma unroll
    for (int k = 0; k < 128; k += 8) {
        wmma::fragment<wmma::matrix_a, 16, 16, 8, wmma::precision::tf32, wmma::row_major> afr[4];
        wmma::fragment<wmma::matrix_b, 16, 16, 8, wmma::precision::tf32, wmma::row_major> bfr[2];
        #pragma unroll
        for (int i = 0; i < 4; i++) {
            wmma::load_matrix_sync(afr[i], &xs[(wm * 64 + i * 16) * 128 + k], 128);
            #pragma unroll
            for (int t = 0; t < afr[i].num_elements; t++)
                afr[i].x[t] = wmma::__float_to_tf32(afr[i].x[t]);
        }
        #pragma unroll
        for (int j = 0; j < 2; j++) {
            wmma::load_matrix_sync(bfr[j], &ws[k * 128 + wn * 32 + j * 16], 128);
            #pragma unroll
            for (int t = 0; t < bfr[j].num_elements; t++)
                bfr[j].x[t] = wmma::__float_to_tf32(bfr[j].x[t]);
        }
        #pragma unroll
        for (int i = 0; i < 4; i++)
            #pragma unroll
            for (int j = 0; j < 2; j++)
                wmma::mma_sync(acc[i][j], afr[i], bfr[j], acc[i][j]);
    }

    #pragma unroll
    for (int i = 0; i < 4; i++) {
        int row = m0 + wm * 64 + i * 16;   // < NNP always (padded)
        #pragma unroll
        for (int j = 0; j < 2; j++)
            wmma::store_matrix_sync(&outp[(size_t)row * 128 + wn * 32 + j * 16],
                                    acc[i][j], 128, wmma::mem_row_major);
    }
    if (blockIdx.x == 0 && blockIdx.y == 0 && tid < 128) {
        g_bnsum[tid] = 0.0; g_bnsq[tid] = 0.0;
    }
}

// ---------------- conv1: warp per node, CSR; softmax+aggregate+alpha in one kernel ------
__global__ void k_score1_csr(const float* __restrict__ att1,
                             float* __restrict__ outAlpha, int writeAlpha) {
    int node = (blockIdx.x * blockDim.x + threadIdx.x) >> 5;
    int lane = threadIdx.x & 31;
    if (node >= NN) return;
    int h = lane >> 3;
    float4 at = *(const float4*)&att1[lane * 4];
    float4 br = *(const float4*)&g_xr1[node * 128 + lane * 4];
    float4 acc = make_float4(0.f, 0.f, 0.f, 0.f);
    float s_acc = 0.f;
    int beg = g_rs[node], end = g_rs[node + 1];

    int sN = g_esrc[beg];
    float4 a = *(const float4*)&g_xl1[sN * 128 + lane * 4];
    for (int j = beg; j < end; j++) {
        float4 cur = a;
        int eid = g_eid[j];
        if (j + 1 < end) {
            sN = g_esrc[j + 1];
            a = *(const float4*)&g_xl1[sN * 128 + lane * 4];
        }
        float p = at.x * lrelu(cur.x + br.x, 0.2f) + at.y * lrelu(cur.y + br.y, 0.2f)
                + at.z * lrelu(cur.z + br.z, 0.2f) + at.w * lrelu(cur.w + br.w, 0.2f);
        p += __shfl_down_sync(0xffffffffu, p, 4, 8);
        p += __shfl_down_sync(0xffffffffu, p, 2, 8);
        p += __shfl_down_sync(0xffffffffu, p, 1, 8);
        float ex = 0.f;
        if ((lane & 7) == 0) {
            ex = __expf(p);
            g_e1[(size_t)eid * 4 + h] = ex;  // original edge order
        }
        float exa = __shfl_sync(0xffffffffu, ex, lane & 24);
        acc.x += cur.x * exa; acc.y += cur.y * exa;
        acc.z += cur.z * exa; acc.w += cur.w * exa;
        s_acc += exa;   // identical across the 8-lane group
    }
    float inv = 1.f / (s_acc + 1e-16f);
    *(float4*)&g_h1[node * 128 + lane * 4] =
        make_float4(acc.x * inv, acc.y * inv, acc.z * inv, acc.w * inv);

    if (writeAlpha) {
        __threadfence_block();
        __syncwarp();
        float s_h = __shfl_sync(0xffffffffu, s_acc, (lane & 3) * 8);
        float inv_h = 1.f / (s_h + 1e-16f);
        for (int j = beg; j < end; j++) {
            int eid = g_eid[j];
            if (lane < 4)
                outAlpha[(size_t)eid * 4 + lane] = g_e1[(size_t)eid * 4 + lane] * inv_h;
        }
    }
}

// ---------------- BN stats (h1 already normalized) ----------------
__global__ void k_bnstat(const float* __restrict__ b1) {
    int c = threadIdx.x;
    double sv = 0.0, qv = 0.0;
    float bb = b1[c];
    for (int r = blockIdx.x; r < NN; r += gridDim.x) {
        float v = g_h1[r * 128 + c] + bb;
        sv += v; qv += (double)v * v;
    }
    atomicAdd(&g_bnsum[c], sv);
    atomicAdd(&g_bnsq[c],  qv);
}

__global__ void k_bnfin(const float* __restrict__ gamma, const float* __restrict__ beta,
                        const float* __restrict__ b1) {
    int c = threadIdx.x;
    double mean = g_bnsum[c] / NN;
    double var  = g_bnsq[c] / NN - mean * mean;
    float sc = gamma[c] * rsqrtf((float)var + 1e-5f);
    g_scale[c] = sc;
    g_shift[c] = (b1[c] - (float)mean) * sc + beta[c];
}

// ---------------- GEMM2 with fused BN+lrelu prologue ----------------
__global__ void k_gemm2(const float* __restrict__ Wl, const float* __restrict__ Wr) {
    extern __shared__ float sm[];
    float* xs = sm;               // 128*128
    float* ws = sm + 128 * 128;   // 128*64
    int tid = threadIdx.x;
    int m0  = blockIdx.x * 128;

    for (int idx = tid * 4; idx < 128 * 64; idx += 512 * 4) {
        int k = idx >> 6, j = idx & 63;
        float4 v = (j < 32) ? *(const float4*)&Wl[k * 32 + j]
                            : *(const float4*)&Wr[k * 32 + j - 32];
        *(float4*)&ws[idx] = v;
    }
    for (int idx = tid * 4; idx < 128 * 128; idx += 512 * 4) {
        int r = idx >> 7, c = idx & 127;
        int row = m0 + r;
        float4 v = make_float4(0.f, 0.f, 0.f, 0.f);
        if (row < NN) {
            float4 hv = *(const float4*)&g_h1[row * 128 + c];
            float4 sc = *(const float4*)&g_scale[c];
            float4 sh = *(const float4*)&g_shift[c];
            v.x = lrelu(hv.x * sc.x + sh.x, 0.01f);
            v.y = lrelu(hv.y * sc.y + sh.y, 0.01f);
            v.z = lrelu(hv.z * sc.z + sh.z, 0.01f);
            v.w = lrelu(hv.w * sc.w + sh.w, 0.01f);
        }
        *(float4*)&xs[idx] = v;
    }
    __syncthreads();

    int n_t = tid & 31, m_t = tid >> 5;
    float acc[8][2];
    #pragma unroll
    for (int a = 0; a < 8; a++) { acc[a][0] = 0.f; acc[a][1] = 0.f; }

    #pragma unroll 4
    for (int k = 0; k < 128; k++) {
        float af[8];
        float b0 = ws[k * 64 + n_t];
        float b1v = ws[k * 64 + n_t + 32];
        #pragma unroll
        for (int mi = 0; mi < 8; mi++) af[mi] = xs[(m_t * 8 + mi) * 128 + k];
        #pragma unroll
        for (int mi = 0; mi < 8; mi++) { acc[mi][0] += af[mi] * b0; acc[mi][1] += af[mi] * b1v; }
    }

    #pragma unroll
    for (int mi = 0; mi < 8; mi++) {
        int row = m0 + m_t * 8 + mi;
        if (row >= NN) continue;
        g_xl2[row * 32 + n_t] = acc[mi][0];
        g_xr2[row * 32 + n_t] = acc[mi][1];
    }
}

// ---------------- conv2: warp per node, CSR; register softmax+aggregate ----------------
__global__ void k_score2_csr(const float* __restrict__ att2) {
    int node = (blockIdx.x * blockDim.x + threadIdx.x) >> 5;
    int lane = threadIdx.x & 31;
    if (node >= NN) return;
    float xr = g_xr2[node * 32 + lane];
    float a2 = att2[lane];
    float acc = 0.f, sacc = 0.f;
    int beg = g_rs[node], end = g_rs[node + 1];

    int sN = g_esrc[beg];
    float xl = g_xl2[sN * 32 + lane];
    for (int j = beg; j < end; j++) {
        float cur = xl;
        if (j + 1 < end) {
            sN = g_esrc[j + 1];
            xl = g_xl2[sN * 32 + lane];
        }
        float p = a2 * lrelu(cur + xr, 0.2f);
        #pragma unroll
        for (int off = 16; off; off >>= 1) p += __shfl_xor_sync(0xffffffffu, p, off);
        float ex = __expf(p);
        acc += cur * ex;
        sacc += ex;
    }
    g_h2[node * 32 + lane] = acc / (sacc + 1e-16f);
}

// ---------------- final: bias + lrelu + Wout + log_softmax ----------------
__global__ void k_final(const float* __restrict__ b2, const float* __restrict__ Wout,
                        const float* __restrict__ bout, float* __restrict__ out) {
    int n = (blockIdx.x * blockDim.x + threadIdx.x) >> 5;
    int lane = threadIdx.x & 31;
    if (n >= NN) return;
    float v = lrelu(g_h2[n * 32 + lane] + b2[lane], 0.01f);
    float l0 = v * Wout[lane * 3 + 0];
    float l1 = v * Wout[lane * 3 + 1];
    float l2 = v * Wout[lane * 3 + 2];
    #pragma unroll
    for (int off = 16; off; off >>= 1) {
        l0 += __shfl_down_sync(0xffffffffu, l0, off);
        l1 += __shfl_down_sync(0xffffffffu, l1, off);
        l2 += __shfl_down_sync(0xffffffffu, l2, off);
    }
    if (lane == 0) {
        l0 += bout[0]; l1 += bout[1]; l2 += bout[2];
        float m = fmaxf(l0, fmaxf(l1, l2));
        float lse = m + logf(expf(l0 - m) + expf(l1 - m) + expf(l2 - m));
        out[n * 3 + 0] = l0 - lse;
        out[n * 3 + 1] = l1 - lse;
        out[n * 3 + 2] = l2 - lse;
    }
}

// ---------------- launch ----------------
extern "C" void kernel_launch(void* const* d_in, const int* in_sizes, int n_in,
                              void* d_out, int out_size) {
    const float* x    = (const float*)d_in[0];
    const void*  ei   = d_in[1];
    const float* Wl1  = (const float*)d_in[2];
    const float* Wr1  = (const float*)d_in[3];
    const float* att1 = (const float*)d_in[4];
    const float* b1   = (const float*)d_in[5];
    const float* gam  = (const float*)d_in[6];
    const float* bet  = (const float*)d_in[7];
    const float* Wl2  = (const float*)d_in[8];
    const float* Wr2  = (const float*)d_in[9];
    const float* att2 = (const float*)d_in[10];
    const float* b2   = (const float*)d_in[11];
    const float* Wout = (const float*)d_in[12];
    const float* bout = (const float*)d_in[13];
    float* out = (float*)d_out;
    float* outAlpha = out + (size_t)NN * 3;
    int writeAlpha = (out_size >= NN * 3 + ET * 4);

    cudaFuncSetAttribute(k_gemm1_tf32, cudaFuncAttributeMaxDynamicSharedMemorySize, 131072);
    cudaFuncSetAttribute(k_gemm2, cudaFuncAttributeMaxDynamicSharedMemorySize, 98304);

    k_detect<<<1, 32>>>(ei);
    k_zero_cnt<<<256, 256>>>();
    k_hist<<<2048, 256>>>(ei);
    k_scanA<<<NB, 256>>>();
    k_scanB<<<1, NB>>>();
    k_scanC<<<NB, 256>>>();
    k_scatter<<<2048, 256>>>(ei);
    dim3 g1((NN + 127) / 128, 2);
    k_gemm1_tf32<<<g1, 256, 131072>>>(x, Wl1, Wr1);
    k_score1_csr<<<(NN * 32 + 255) / 256, 256>>>(att1, outAlpha, writeAlpha);
    k_bnstat<<<1024, 128>>>(b1);
    k_bnfin<<<1, 128>>>(gam, bet, b1);
    k_gemm2<<<(NN + 127) / 128, 512, 98304>>>(Wl2, Wr2);
    k_score2_csr<<<(NN * 32 + 255) / 256, 256>>>(att2);
    k_final<<<(NN + 7) / 8, 256>>>(b2, Wout, bout, out);
}

// round 16
// speedup vs baseline: 1.0019x; 1.0019x over previous
#include <cuda_runtime.h>
#include <cstdint>

#define NN 100000
#define EE 1600000
#define ET (EE + NN)            // 1,700,000 edges incl self loops

#define NB 256                  // scan blocks
#define CB 391                  // ceil(NN/NB)
#define TS 2                    // elems per thread in scan block

// ---------------- scratch (device globals; no runtime alloc) ----------------
__device__ __align__(16) float  g_xl1[NN * 128];
__device__ __align__(16) float  g_xr1[NN * 128];
__device__ __align__(16) float  g_h1 [NN * 128];   // normalized conv1 output (pre-BN)
__device__ __align__(16) float  g_e1 [ET * 4];     // exp(score), ORIGINAL edge order
__device__ __align__(16) double g_bnsum[128];
__device__ __align__(16) double g_bnsq [128];
__device__ __align__(16) float  g_scale[128];
__device__ __align__(16) float  g_shift[128];      // includes b1 & beta & mean folded
__device__ __align__(16) float  g_xl2[NN * 32];
__device__ __align__(16) float  g_xr2[NN * 32];
__device__ __align__(16) float  g_h2 [NN * 32];    // normalized conv2 output
// CSR edge structure (dst-sorted)
__device__ int g_cnt [NN];
__device__ int g_rs  [NN + 1];
__device__ int g_bsum[NB];
__device__ int g_esrc[ET];
__device__ int g_eid [ET];
__device__ int g_ei64;

__device__ __forceinline__ float lrelu(float v, float s) { return v > 0.f ? v : s * v; }

__device__ __forceinline__ void edge_sd(const void* __restrict__ ei, int use64,
                                        int e, int& s, int& d) {
    if (e < EE) {
        if (use64) {
            const long long* p = (const long long*)ei;
            s = (int)p[e]; d = (int)p[EE + e];
        } else {
            const int* p = (const int*)ei;
            s = p[e]; d = p[EE + e];
        }
    } else { s = e - EE; d = e - EE; }
}

__device__ __forceinline__ int edge_d(const void* __restrict__ ei, int use64, int e) {
    if (e < EE) {
        if (use64) return (int)((const long long*)ei)[EE + e];
        return ((const int*)ei)[EE + e];
    }
    return e - EE;
}

// ---------------- dtype probe ----------------
__global__ void k_detect(const void* __restrict__ ei) {
    if (threadIdx.x == 0 && blockIdx.x == 0) {
        const long long* p = (const long long*)ei;
        int ok = 1;
        #pragma unroll
        for (int i = 0; i < 8; i++) {
            long long v = p[i];
            if (v < 0 || v >= NN) ok = 0;
        }
        g_ei64 = ok;
    }
}

// ---------------- CSR build ----------------
__global__ void k_zero_cnt() {
    int i = blockIdx.x * blockDim.x + threadIdx.x;
    int st = gridDim.x * blockDim.x;
    for (; i < NN; i += st) g_cnt[i] = 0;
}

__global__ void k_hist(const void* __restrict__ ei) {
    int i = blockIdx.x * blockDim.x + threadIdx.x;
    int st = gridDim.x * blockDim.x;
    int use64 = g_ei64;
    for (; i < ET; i += st) atomicAdd(&g_cnt[edge_d(ei, use64, i)], 1);
}

__global__ void k_scanA() {
    int b = blockIdx.x, t = threadIdx.x;
    int lo = b * CB + t * TS;
    int hi = min(b * CB + CB, NN);
    int s = 0;
    #pragma unroll
    for (int k = 0; k < TS; k++) {
        int i = lo + k;
        if (i < hi) s += g_cnt[i];
    }
    __shared__ int sh[256];
    sh[t] = s; __syncthreads();
    for (int off = 128; off; off >>= 1) {
        if (t < off) sh[t] += sh[t + off];
        __syncthreads();
    }
    if (t == 0) g_bsum[b] = sh[0];
}

__global__ void k_scanB() {
    __shared__ int sh[NB];
    int t = threadIdx.x;
    sh[t] = g_bsum[t]; __syncthreads();
    for (int off = 1; off < NB; off <<= 1) {
        int v = (t >= off) ? sh[t - off] : 0;
        __syncthreads();
        sh[t] += v;
        __syncthreads();
    }
    g_bsum[t] = t ? sh[t - 1] : 0;
}

__global__ void k_scanC() {
    int b = blockIdx.x, t = threadIdx.x;
    int lo = b * CB + t * TS;
    int hi = min(b * CB + CB, NN);
    int s = 0;
    #pragma unroll
    for (int k = 0; k < TS; k++) {
        int i = lo + k;
        if (i < hi) s += g_cnt[i];
    }
    __shared__ int sh[256];
    sh[t] = s; __syncthreads();
    for (int off = 1; off < 256; off <<= 1) {
        int v = (t >= off) ? sh[t - off] : 0;
        __syncthreads();
        sh[t] += v;
        __syncthreads();
    }
    int run = g_bsum[b] + (t ? sh[t - 1] : 0);
    #pragma unroll
    for (int k = 0; k < TS; k++) {
        int i = lo + k;
        if (i < hi) {
            int c = g_cnt[i];
            g_rs[i] = run;
            run += c;
            g_cnt[i] = 0;
        }
    }
    if (b == 0 && t == 0) g_rs[NN] = ET;
}

__global__ void k_scatter(const void* __restrict__ ei) {
    int i = blockIdx.x * blockDim.x + threadIdx.x;
    int st = gridDim.x * blockDim.x;
    int use64 = g_ei64;
    for (; i < ET; i += st) {
        int s, d; edge_sd(ei, use64, i, s, d);
        int pos = g_rs[d] + atomicAdd(&g_cnt[d], 1);
        g_esrc[pos] = s;
        g_eid[pos]  = i;
    }
}

// ---------------- GEMM1: [xl1|xr1] = x @ [Wl1|Wr1], BM=128 BN=256, 512 thr (fp32) ------
__global__ void k_gemm1(const float* __restrict__ x,
                        const float* __restrict__ Wl, const float* __restrict__ Wr) {
    extern __shared__ float sm[];
    float* xs = sm;               // 128*128
    float* ws = sm + 128 * 128;   // 128*256
    int tid = threadIdx.x;
    int m0  = blockIdx.x * 128;

    for (int idx = tid * 4; idx < 128 * 256; idx += 512 * 4) {
        int k = idx >> 8, j = idx & 255;
        float4 v = (j < 128) ? *(const float4*)&Wl[k * 128 + j]
                             : *(const float4*)&Wr[k * 128 + j - 128];
        *(float4*)&ws[idx] = v;
    }
    for (int idx = tid * 4; idx < 128 * 128; idx += 512 * 4) {
        int r = idx >> 7, c = idx & 127;
        int row = m0 + r;
        float4 v = make_float4(0.f, 0.f, 0.f, 0.f);
        if (row < NN) v = *(const float4*)&x[row * 128 + c];
        *(float4*)&xs[idx] = v;
    }
    __syncthreads();

    int n_t = tid & 31, m_t = tid >> 5;
    float acc[8][8];
    #pragma unroll
    for (int a = 0; a < 8; a++)
        #pragma unroll
        for (int b = 0; b < 8; b++) acc[a][b] = 0.f;

    #pragma unroll 4
    for (int k = 0; k < 128; k++) {
        float af[8], bf[8];
        #pragma unroll
        for (int mi = 0; mi < 8; mi++) af[mi] = xs[(m_t * 8 + mi) * 128 + k];
        #pragma unroll
        for (int ni = 0; ni < 8; ni++) bf[ni] = ws[k * 256 + n_t + 32 * ni];
        #pragma unroll
        for (int mi = 0; mi < 8; mi++)
            #pragma unroll
            for (int ni = 0; ni < 8; ni++) acc[mi][ni] += af[mi] * bf[ni];
    }

    #pragma unroll
    for (int mi = 0; mi < 8; mi++) {
        int row = m0 + m_t * 8 + mi;
        if (row >= NN) continue;
        #pragma unroll
        for (int ni = 0; ni < 4; ni++)
            g_xl1[row * 128 + n_t + 32 * ni] = acc[mi][ni];
        #pragma unroll
        for (int ni = 4; ni < 8; ni++)
            g_xr1[row * 128 + n_t + 32 * (ni - 4)] = acc[mi][ni];
    }
    if (blockIdx.x == 0 && tid < 128) { g_bnsum[tid] = 0.0; g_bnsq[tid] = 0.0; }
}

// ---------------- conv1: warp per node, CSR; softmax+aggregate+alpha, depth-2 prefetch --
__global__ void k_score1_csr(const float* __restrict__ att1,
                             float* __restrict__ outAlpha, int writeAlpha) {
    int node = (blockIdx.x * blockDim.x + threadIdx.x) >> 5;
    int lane = threadIdx.x & 31;
    if (node >= NN) return;
    int h = lane >> 3;
    float4 at = *(const float4*)&att1[lane * 4];
    float4 br = *(const float4*)&g_xr1[node * 128 + lane * 4];
    float4 acc = make_float4(0.f, 0.f, 0.f, 0.f);
    float s_acc = 0.f;
    int beg = g_rs[node], end = g_rs[node + 1];

    float4 a0 = *(const float4*)&g_xl1[g_esrc[beg] * 128 + lane * 4];
    float4 a1 = (beg + 1 < end)
        ? *(const float4*)&g_xl1[g_esrc[beg + 1] * 128 + lane * 4] : a0;
    for (int j = beg; j < end; j++) {
        float4 cur = a0;
        int eid = g_eid[j];
        a0 = a1;
        if (j + 2 < end)
            a1 = *(const float4*)&g_xl1[g_esrc[j + 2] * 128 + lane * 4];
        float p = at.x * lrelu(cur.x + br.x, 0.2f) + at.y * lrelu(cur.y + br.y, 0.2f)
                + at.z * lrelu(cur.z + br.z, 0.2f) + at.w * lrelu(cur.w + br.w, 0.2f);
        p += __shfl_down_sync(0xffffffffu, p, 4, 8);
        p += __shfl_down_sync(0xffffffffu, p, 2, 8);
        p += __shfl_down_sync(0xffffffffu, p, 1, 8);
        float ex = 0.f;
        if ((lane & 7) == 0) {
            ex = __expf(p);
            g_e1[(size_t)eid * 4 + h] = ex;  // original edge order
        }
        float exa = __shfl_sync(0xffffffffu, ex, lane & 24);
        acc.x += cur.x * exa; acc.y += cur.y * exa;
        acc.z += cur.z * exa; acc.w += cur.w * exa;
        s_acc += exa;   // identical across the 8-lane group
    }
    float inv = 1.f / (s_acc + 1e-16f);
    *(float4*)&g_h1[node * 128 + lane * 4] =
        make_float4(acc.x * inv, acc.y * inv, acc.z * inv, acc.w * inv);

    if (writeAlpha) {
        __threadfence_block();
        __syncwarp();
        float s_h = __shfl_sync(0xffffffffu, s_acc, (lane & 3) * 8);
        float inv_h = 1.f / (s_h + 1e-16f);
        for (int j = beg; j < end; j++) {
            int eid = g_eid[j];
            if (lane < 4)
                outAlpha[(size_t)eid * 4 + lane] = g_e1[(size_t)eid * 4 + lane] * inv_h;
        }
    }
}

// ---------------- BN stats (h1 already normalized) ----------------
__global__ void k_bnstat(const float* __restrict__ b1) {
    int c = threadIdx.x;
    double sv = 0.0, qv = 0.0;
    float bb = b1[c];
    for (int r = blockIdx.x; r < NN; r += gridDim.x) {
        float v = g_h1[r * 128 + c] + bb;
        sv += v; qv += (double)v * v;
    }
    atomicAdd(&g_bnsum[c], sv);
    atomicAdd(&g_bnsq[c],  qv);
}

__global__ void k_bnfin(const float* __restrict__ gamma, const float* __restrict__ beta,
                        const float* __restrict__ b1) {
    int c = threadIdx.x;
    double mean = g_bnsum[c] / NN;
    double var  = g_bnsq[c] / NN - mean * mean;
    float sc = gamma[c] * rsqrtf((float)var + 1e-5f);
    g_scale[c] = sc;
    g_shift[c] = (b1[c] - (float)mean) * sc + beta[c];
}

// ---------------- GEMM2 with fused BN+lrelu prologue ----------------
__global__ void k_gemm2(const float* __restrict__ Wl, const float* __restrict__ Wr) {
    extern __shared__ float sm[];
    float* xs = sm;               // 128*128
    float* ws = sm + 128 * 128;   // 128*64
    int tid = threadIdx.x;
    int m0  = blockIdx.x * 128;

    for (int idx = tid * 4; idx < 128 * 64; idx += 512 * 4) {
        int k = idx >> 6, j = idx & 63;
        float4 v = (j < 32) ? *(const float4*)&Wl[k * 32 + j]
                            : *(const float4*)&Wr[k * 32 + j - 32];
        *(float4*)&ws[idx] = v;
    }
    for (int idx = tid * 4; idx < 128 * 128; idx += 512 * 4) {
        int r = idx >> 7, c = idx & 127;
        int row = m0 + r;
        float4 v = make_float4(0.f, 0.f, 0.f, 0.f);
        if (row < NN) {
            float4 hv = *(const float4*)&g_h1[row * 128 + c];
            float4 sc = *(const float4*)&g_scale[c];
            float4 sh = *(const float4*)&g_shift[c];
            v.x = lrelu(hv.x * sc.x + sh.x, 0.01f);
            v.y = lrelu(hv.y * sc.y + sh.y, 0.01f);
            v.z = lrelu(hv.z * sc.z + sh.z, 0.01f);
            v.w = lrelu(hv.w * sc.w + sh.w, 0.01f);
        }
        *(float4*)&xs[idx] = v;
    }
    __syncthreads();

    int n_t = tid & 31, m_t = tid >> 5;
    float acc[8][2];
    #pragma unroll
    for (int a = 0; a < 8; a++) { acc[a][0] = 0.f; acc[a][1] = 0.f; }

    #pragma unroll 4
    for (int k = 0; k < 128; k++) {
        float af[8];
        float b0 = ws[k * 64 + n_t];
        float b1v = ws[k * 64 + n_t + 32];
        #pragma unroll
        for (int mi = 0; mi < 8; mi++) af[mi] = xs[(m_t * 8 + mi) * 128 + k];
        #pragma unroll
        for (int mi = 0; mi < 8; mi++) { acc[mi][0] += af[mi] * b0; acc[mi][1] += af[mi] * b1v; }
    }

    #pragma unroll
    for (int mi = 0; mi < 8; mi++) {
        int row = m0 + m_t * 8 + mi;
        if (row >= NN) continue;
        g_xl2[row * 32 + n_t] = acc[mi][0];
        g_xr2[row * 32 + n_t] = acc[mi][1];
    }
}

// ---------------- conv2: warp per node, CSR; register softmax+aggregate ----------------
__global__ void k_score2_csr(const float* __restrict__ att2) {
    int node = (blockIdx.x * blockDim.x + threadIdx.x) >> 5;
    int lane = threadIdx.x & 31;
    if (node >= NN) return;
    float xr = g_xr2[node * 32 + lane];
    float a2 = att2[lane];
    float acc = 0.f, sacc = 0.f;
    int beg = g_rs[node], end = g_rs[node + 1];

    float x0 = g_xl2[g_esrc[beg] * 32 + lane];
    float x1 = (beg + 1 < end) ? g_xl2[g_esrc[beg + 1] * 32 + lane] : x0;
    for (int j = beg; j < end; j++) {
        float cur = x0;
        x0 = x1;
        if (j + 2 < end) x1 = g_xl2[g_esrc[j + 2] * 32 + lane];
        float p = a2 * lrelu(cur + xr, 0.2f);
        #pragma unroll
        for (int off = 16; off; off >>= 1) p += __shfl_xor_sync(0xffffffffu, p, off);
        float ex = __expf(p);
        acc += cur * ex;
        sacc += ex;
    }
    g_h2[node * 32 + lane] = acc / (sacc + 1e-16f);
}

// ---------------- final: bias + lrelu + Wout + log_softmax ----------------
__global__ void k_final(const float* __restrict__ b2, const float* __restrict__ Wout,
                        const float* __restrict__ bout, float* __restrict__ out) {
    int n = (blockIdx.x * blockDim.x + threadIdx.x) >> 5;
    int lane = threadIdx.x & 31;
    if (n >= NN) return;
    float v = lrelu(g_h2[n * 32 + lane] + b2[lane], 0.01f);
    float l0 = v * Wout[lane * 3 + 0];
    float l1 = v * Wout[lane * 3 + 1];
    float l2 = v * Wout[lane * 3 + 2];
    #pragma unroll
    for (int off = 16; off; off >>= 1) {
        l0 += __shfl_down_sync(0xffffffffu, l0, off);
        l1 += __shfl_down_sync(0xffffffffu, l1, off);
        l2 += __shfl_down_sync(0xffffffffu, l2, off);
    }
    if (lane == 0) {
        l0 += bout[0]; l1 += bout[1]; l2 += bout[2];
        float m = fmaxf(l0, fmaxf(l1, l2));
        float lse = m + logf(expf(l0 - m) + expf(l1 - m) + expf(l2 - m));
        out[n * 3 + 0] = l0 - lse;
        out[n * 3 + 1] = l1 - lse;
        out[n * 3 + 2] = l2 - lse;
    }
}

// ---------------- launch (single stream; no static CUDA init) ----------------
extern "C" void kernel_launch(void* const* d_in, const int* in_sizes, int n_in,
                              void* d_out, int out_size) {
    const float* x    = (const float*)d_in[0];
    const void*  ei   = d_in[1];
    const float* Wl1  = (const float*)d_in[2];
    const float* Wr1  = (const float*)d_in[3];
    const float* att1 = (const float*)d_in[4];
    const float* b1   = (const float*)d_in[5];
    const float* gam  = (const float*)d_in[6];
    const float* bet  = (const float*)d_in[7];
    const float* Wl2  = (const float*)d_in[8];
    const float* Wr2  = (const float*)d_in[9];
    const float* att2 = (const float*)d_in[10];
    const float* b2   = (const float*)d_in[11];
    const float* Wout = (const float*)d_in[12];
    const float* bout = (const float*)d_in[13];
    float* out = (float*)d_out;
    float* outAlpha = out + (size_t)NN * 3;
    int writeAlpha = (out_size >= NN * 3 + ET * 4);

    cudaFuncSetAttribute(k_gemm1, cudaFuncAttributeMaxDynamicSharedMemorySize, 196608);
    cudaFuncSetAttribute(k_gemm2, cudaFuncAttributeMaxDynamicSharedMemorySize, 98304);

    k_detect<<<1, 32>>>(ei);
    k_zero_cnt<<<256, 256>>>();
    k_hist<<<2048, 256>>>(ei);
    k_scanA<<<NB, 256>>>();
    k_scanB<<<1, NB>>>();
    k_scanC<<<NB, 256>>>();
    k_scatter<<<2048, 256>>>(ei);
    k_gemm1<<<(NN + 127) / 128, 512, 196608>>>(x, Wl1, Wr1);
    k_score1_csr<<<(NN * 32 + 255) / 256, 256>>>(att1, outAlpha, writeAlpha);
    k_bnstat<<<1024, 128>>>(b1);
    k_bnfin<<<1, 128>>>(gam, bet, b1);
    k_gemm2<<<(NN + 127) / 128, 512, 98304>>>(Wl2, Wr2);
    k_score2_csr<<<(NN * 32 + 255) / 256, 256>>>(att2);
    k_final<<<(NN + 7) / 8, 256>>>(b2, Wout, bout, out);
}

// round 17
// speedup vs baseline: 1.1541x; 1.1519x over previous
#include <cuda_runtime.h>
#include <cstdint>

#define NN 100000
#define EE 1600000
#define ET (EE + NN)            // 1,700,000 edges incl self loops

#define NB 256                  // scan blocks
#define CB 391                  // ceil(NN/NB)
#define TS 2                    // elems per thread in scan block

// ---------------- scratch (device globals; no runtime alloc) ----------------
__device__ __align__(16) float  g_xl1[NN * 128];
__device__ __align__(16) float  g_xr1[NN * 128];
__device__ __align__(16) float  g_h1 [NN * 128];   // normalized conv1 output (pre-BN)
__device__ __align__(16) float  g_e1 [ET * 4];     // exp(score), ORIGINAL edge order
__device__ __align__(16) double g_bnsum[128];
__device__ __align__(16) double g_bnsq [128];
__device__ __align__(16) float  g_scale[128];
__device__ __align__(16) float  g_shift[128];      // includes b1 & beta & mean folded
__device__ __align__(16) float  g_xl2[NN * 32];
__device__ __align__(16) float  g_xr2[NN * 32];
__device__ __align__(16) float  g_h2 [NN * 32];    // normalized conv2 output
// CSR edge structure (dst-sorted)
__device__ int g_cnt [NN];
__device__ int g_rs  [NN + 1];
__device__ int g_bsum[NB];
__device__ int g_esrc[ET];
__device__ int g_eid [ET];
__device__ int g_ei64;

__device__ __forceinline__ float lrelu(float v, float s) { return v > 0.f ? v : s * v; }

__device__ __forceinline__ void edge_sd(const void* __restrict__ ei, int use64,
                                        int e, int& s, int& d) {
    if (e < EE) {
        if (use64) {
            const long long* p = (const long long*)ei;
            s = (int)p[e]; d = (int)p[EE + e];
        } else {
            const int* p = (const int*)ei;
            s = p[e]; d = p[EE + e];
        }
    } else { s = e - EE; d = e - EE; }
}

__device__ __forceinline__ int edge_d(const void* __restrict__ ei, int use64, int e) {
    if (e < EE) {
        if (use64) return (int)((const long long*)ei)[EE + e];
        return ((const int*)ei)[EE + e];
    }
    return e - EE;
}

// ---------------- zero counters + dtype probe (merged) ----------------
__global__ void k_zero_cnt(const void* __restrict__ ei) {
    int i = blockIdx.x * blockDim.x + threadIdx.x;
    int st = gridDim.x * blockDim.x;
    for (; i < NN; i += st) g_cnt[i] = 0;
    if (blockIdx.x == 0 && threadIdx.x == 0) {
        const long long* p = (const long long*)ei;
        int ok = 1;
        #pragma unroll
        for (int k = 0; k < 8; k++) {
            long long v = p[k];
            if (v < 0 || v >= NN) ok = 0;
        }
        g_ei64 = ok;
    }
}

__global__ void k_hist(const void* __restrict__ ei) {
    int i = blockIdx.x * blockDim.x + threadIdx.x;
    int st = gridDim.x * blockDim.x;
    int use64 = g_ei64;
    for (; i < ET; i += st) atomicAdd(&g_cnt[edge_d(ei, use64, i)], 1);
}

__global__ void k_scanA() {
    int b = blockIdx.x, t = threadIdx.x;
    int lo = b * CB + t * TS;
    int hi = min(b * CB + CB, NN);
    int s = 0;
    #pragma unroll
    for (int k = 0; k < TS; k++) {
        int i = lo + k;
        if (i < hi) s += g_cnt[i];
    }
    __shared__ int sh[256];
    sh[t] = s; __syncthreads();
    for (int off = 128; off; off >>= 1) {
        if (t < off) sh[t] += sh[t + off];
        __syncthreads();
    }
    if (t == 0) g_bsum[b] = sh[0];
}

__global__ void k_scanB() {
    __shared__ int sh[NB];
    int t = threadIdx.x;
    sh[t] = g_bsum[t]; __syncthreads();
    for (int off = 1; off < NB; off <<= 1) {
        int v = (t >= off) ? sh[t - off] : 0;
        __syncthreads();
        sh[t] += v;
        __syncthreads();
    }
    g_bsum[t] = t ? sh[t - 1] : 0;
}

__global__ void k_scanC() {
    int b = blockIdx.x, t = threadIdx.x;
    int lo = b * CB + t * TS;
    int hi = min(b * CB + CB, NN);
    int s = 0;
    #pragma unroll
    for (int k = 0; k < TS; k++) {
        int i = lo + k;
        if (i < hi) s += g_cnt[i];
    }
    __shared__ int sh[256];
    sh[t] = s; __syncthreads();
    for (int off = 1; off < 256; off <<= 1) {
        int v = (t >= off) ? sh[t - off] : 0;
        __syncthreads();
        sh[t] += v;
        __syncthreads();
    }
    int run = g_bsum[b] + (t ? sh[t - 1] : 0);
    #pragma unroll
    for (int k = 0; k < TS; k++) {
        int i = lo + k;
        if (i < hi) {
            int c = g_cnt[i];
            g_rs[i] = run;
            run += c;
            g_cnt[i] = 0;
        }
    }
    if (b == 0 && t == 0) g_rs[NN] = ET;
}

__global__ void k_scatter(const void* __restrict__ ei) {
    int i = blockIdx.x * blockDim.x + threadIdx.x;
    int st = gridDim.x * blockDim.x;
    int use64 = g_ei64;
    for (; i < ET; i += st) {
        int s, d; edge_sd(ei, use64, i, s, d);
        int pos = g_rs[d] + atomicAdd(&g_cnt[d], 1);
        g_esrc[pos] = s;
        g_eid[pos]  = i;
    }
}

// ---------------- GEMM1: [xl1|xr1] = x @ [Wl1|Wr1], BM=128 BN=256, 512 thr (fp32) ------
__global__ void k_gemm1(const float* __restrict__ x,
                        const float* __restrict__ Wl, const float* __restrict__ Wr) {
    extern __shared__ float sm[];
    float* xs = sm;               // 128*128
    float* ws = sm + 128 * 128;   // 128*256
    int tid = threadIdx.x;
    int m0  = blockIdx.x * 128;

    for (int idx = tid * 4; idx < 128 * 256; idx += 512 * 4) {
        int k = idx >> 8, j = idx & 255;
        float4 v = (j < 128) ? *(const float4*)&Wl[k * 128 + j]
                             : *(const float4*)&Wr[k * 128 + j - 128];
        *(float4*)&ws[idx] = v;
    }
    for (int idx = tid * 4; idx < 128 * 128; idx += 512 * 4) {
        int r = idx >> 7, c = idx & 127;
        int row = m0 + r;
        float4 v = make_float4(0.f, 0.f, 0.f, 0.f);
        if (row < NN) v = *(const float4*)&x[row * 128 + c];
        *(float4*)&xs[idx] = v;
    }
    __syncthreads();

    int n_t = tid & 31, m_t = tid >> 5;
    float acc[8][8];
    #pragma unroll
    for (int a = 0; a < 8; a++)
        #pragma unroll
        for (int b = 0; b < 8; b++) acc[a][b] = 0.f;

    #pragma unroll 4
    for (int k = 0; k < 128; k++) {
        float af[8], bf[8];
        #pragma unroll
        for (int mi = 0; mi < 8; mi++) af[mi] = xs[(m_t * 8 + mi) * 128 + k];
        #pragma unroll
        for (int ni = 0; ni < 8; ni++) bf[ni] = ws[k * 256 + n_t + 32 * ni];
        #pragma unroll
        for (int mi = 0; mi < 8; mi++)
            #pragma unroll
            for (int ni = 0; ni < 8; ni++) acc[mi][ni] += af[mi] * bf[ni];
    }

    #pragma unroll
    for (int mi = 0; mi < 8; mi++) {
        int row = m0 + m_t * 8 + mi;
        if (row >= NN) continue;
        #pragma unroll
        for (int ni = 0; ni < 4; ni++)
            g_xl1[row * 128 + n_t + 32 * ni] = acc[mi][ni];
        #pragma unroll
        for (int ni = 4; ni < 8; ni++)
            g_xr1[row * 128 + n_t + 32 * (ni - 4)] = acc[mi][ni];
    }
    if (blockIdx.x == 0 && tid < 128) { g_bnsum[tid] = 0.0; g_bnsq[tid] = 0.0; }
}

// ---------------- conv1: warp per node, CSR; depth-1 prefetch (proven form) ------------
__global__ void k_score1_csr(const float* __restrict__ att1,
                             float* __restrict__ outAlpha, int writeAlpha) {
    int node = (blockIdx.x * blockDim.x + threadIdx.x) >> 5;
    int lane = threadIdx.x & 31;
    if (node >= NN) return;
    int h = lane >> 3;
    float4 at = *(const float4*)&att1[lane * 4];
    float4 br = *(const float4*)&g_xr1[node * 128 + lane * 4];
    float4 acc = make_float4(0.f, 0.f, 0.f, 0.f);
    float s_acc = 0.f;
    int beg = g_rs[node], end = g_rs[node + 1];

    int sN = g_esrc[beg];
    float4 a = *(const float4*)&g_xl1[sN * 128 + lane * 4];
    for (int j = beg; j < end; j++) {
        float4 cur = a;
        int eid = g_eid[j];
        if (j + 1 < end) {
            sN = g_esrc[j + 1];
            a = *(const float4*)&g_xl1[sN * 128 + lane * 4];
        }
        float p = at.x * lrelu(cur.x + br.x, 0.2f) + at.y * lrelu(cur.y + br.y, 0.2f)
                + at.z * lrelu(cur.z + br.z, 0.2f) + at.w * lrelu(cur.w + br.w, 0.2f);
        p += __shfl_down_sync(0xffffffffu, p, 4, 8);
        p += __shfl_down_sync(0xffffffffu, p, 2, 8);
        p += __shfl_down_sync(0xffffffffu, p, 1, 8);
        float ex = 0.f;
        if ((lane & 7) == 0) {
            ex = __expf(p);
            g_e1[(size_t)eid * 4 + h] = ex;  // original edge order
        }
        float exa = __shfl_sync(0xffffffffu, ex, lane & 24);
        acc.x += cur.x * exa; acc.y += cur.y * exa;
        acc.z += cur.z * exa; acc.w += cur.w * exa;
        s_acc += exa;   // identical across the 8-lane group
    }
    float inv = 1.f / (s_acc + 1e-16f);
    *(float4*)&g_h1[node * 128 + lane * 4] =
        make_float4(acc.x * inv, acc.y * inv, acc.z * inv, acc.w * inv);

    if (writeAlpha) {
        // leader-lane g_e1 writes -> visible to all lanes
        __threadfence_block();
        __syncwarp();
        // 8 edges per iteration: lane -> (edge = lane>>2, head = lane&3)
        int hh = lane & 3;
        float s_h = __shfl_sync(0xffffffffu, s_acc, hh * 8);
        float inv_h = 1.f / (s_h + 1e-16f);
        int eoff = lane >> 2;
        for (int j0 = beg; j0 < end; j0 += 8) {
            int jj = j0 + eoff;
            if (jj < end) {
                int eid = g_eid[jj];
                outAlpha[(size_t)eid * 4 + hh] = g_e1[(size_t)eid * 4 + hh] * inv_h;
            }
        }
    }
}

// ---------------- BN stats (h1 already normalized) ----------------
__global__ void k_bnstat(const float* __restrict__ b1) {
    int c = threadIdx.x;
    double sv = 0.0, qv = 0.0;
    float bb = b1[c];
    for (int r = blockIdx.x; r < NN; r += gridDim.x) {
        float v = g_h1[r * 128 + c] + bb;
        sv += v; qv += (double)v * v;
    }
    atomicAdd(&g_bnsum[c], sv);
    atomicAdd(&g_bnsq[c],  qv);
}

__global__ void k_bnfin(const float* __restrict__ gamma, const float* __restrict__ beta,
                        const float* __restrict__ b1) {
    int c = threadIdx.x;
    double mean = g_bnsum[c] / NN;
    double var  = g_bnsq[c] / NN - mean * mean;
    float sc = gamma[c] * rsqrtf((float)var + 1e-5f);
    g_scale[c] = sc;
    g_shift[c] = (b1[c] - (float)mean) * sc + beta[c];
}

// ---------------- GEMM2 with fused BN+lrelu prologue ----------------
__global__ void k_gemm2(const float* __restrict__ Wl, const float* __restrict__ Wr) {
    extern __shared__ float sm[];
    float* xs = sm;               // 128*128
    float* ws = sm + 128 * 128;   // 128*64
    int tid = threadIdx.x;
    int m0  = blockIdx.x * 128;

    for (int idx = tid * 4; idx < 128 * 64; idx += 512 * 4) {
        int k = idx >> 6, j = idx & 63;
        float4 v = (j < 32) ? *(const float4*)&Wl[k * 32 + j]
                            : *(const float4*)&Wr[k * 32 + j - 32];
        *(float4*)&ws[idx] = v;
    }
    for (int idx = tid * 4; idx < 128 * 128; idx += 512 * 4) {
        int r = idx >> 7, c = idx & 127;
        int row = m0 + r;
        float4 v = make_float4(0.f, 0.f, 0.f, 0.f);
        if (row < NN) {
            float4 hv = *(const float4*)&g_h1[row * 128 + c];
            float4 sc = *(const float4*)&g_scale[c];
            float4 sh = *(const float4*)&g_shift[c];
            v.x = lrelu(hv.x * sc.x + sh.x, 0.01f);
            v.y = lrelu(hv.y * sc.y + sh.y, 0.01f);
            v.z = lrelu(hv.z * sc.z + sh.z, 0.01f);
            v.w = lrelu(hv.w * sc.w + sh.w, 0.01f);
        }
        *(float4*)&xs[idx] = v;
    }
    __syncthreads();

    int n_t = tid & 31, m_t = tid >> 5;
    float acc[8][2];
    #pragma unroll
    for (int a = 0; a < 8; a++) { acc[a][0] = 0.f; acc[a][1] = 0.f; }

    #pragma unroll 4
    for (int k = 0; k < 128; k++) {
        float af[8];
        float b0 = ws[k * 64 + n_t];
        float b1v = ws[k * 64 + n_t + 32];
        #pragma unroll
        for (int mi = 0; mi < 8; mi++) af[mi] = xs[(m_t * 8 + mi) * 128 + k];
        #pragma unroll
        for (int mi = 0; mi < 8; mi++) { acc[mi][0] += af[mi] * b0; acc[mi][1] += af[mi] * b1v; }
    }

    #pragma unroll
    for (int mi = 0; mi < 8; mi++) {
        int row = m0 + m_t * 8 + mi;
        if (row >= NN) continue;
        g_xl2[row * 32 + n_t] = acc[mi][0];
        g_xr2[row * 32 + n_t] = acc[mi][1];
    }
}

// ---------------- conv2: warp per node, CSR; depth-1 prefetch (proven form) ------------
__global__ void k_score2_csr(const float* __restrict__ att2) {
    int node = (blockIdx.x * blockDim.x + threadIdx.x) >> 5;
    int lane = threadIdx.x & 31;
    if (node >= NN) return;
    float xr = g_xr2[node * 32 + lane];
    float a2 = att2[lane];
    float acc = 0.f, sacc = 0.f;
    int beg = g_rs[node], end = g_rs[node + 1];

    int sN = g_esrc[beg];
    float xl = g_xl2[sN * 32 + lane];
    for (int j = beg; j < end; j++) {
        float cur = xl;
        if (j + 1 < end) {
            sN = g_esrc[j + 1];
            xl = g_xl2[sN * 32 + lane];
        }
        float p = a2 * lrelu(cur + xr, 0.2f);
        #pragma unroll
        for (int off = 16; off; off >>= 1) p += __shfl_xor_sync(0xffffffffu, p, off);
        float ex = __expf(p);
        acc += cur * ex;
        sacc += ex;
    }
    g_h2[node * 32 + lane] = acc / (sacc + 1e-16f);
}

// ---------------- final: bias + lrelu + Wout + log_softmax ----------------
__global__ void k_final(const float* __restrict__ b2, const float* __restrict__ Wout,
                        const float* __restrict__ bout, float* __restrict__ out) {
    int n = (blockIdx.x * blockDim.x + threadIdx.x) >> 5;
    int lane = threadIdx.x & 31;
    if (n >= NN) return;
    float v = lrelu(g_h2[n * 32 + lane] + b2[lane], 0.01f);
    float l0 = v * Wout[lane * 3 + 0];
    float l1 = v * Wout[lane * 3 + 1];
    float l2 = v * Wout[lane * 3 + 2];
    #pragma unroll
    for (int off = 16; off; off >>= 1) {
        l0 += __shfl_down_sync(0xffffffffu, l0, off);
        l1 += __shfl_down_sync(0xffffffffu, l1, off);
        l2 += __shfl_down_sync(0xffffffffu, l2, off);
    }
    if (lane == 0) {
        l0 += bout[0]; l1 += bout[1]; l2 += bout[2];
        float m = fmaxf(l0, fmaxf(l1, l2));
        float lse = m + logf(expf(l0 - m) + expf(l1 - m) + expf(l2 - m));
        out[n * 3 + 0] = l0 - lse;
        out[n * 3 + 1] = l1 - lse;
        out[n * 3 + 2] = l2 - lse;
    }
}

// ---------------- launch (single stream; no static CUDA init) ----------------
extern "C" void kernel_launch(void* const* d_in, const int* in_sizes, int n_in,
                              void* d_out, int out_size) {
    const float* x    = (const float*)d_in[0];
    const void*  ei   = d_in[1];
    const float* Wl1  = (const float*)d_in[2];
    const float* Wr1  = (const float*)d_in[3];
    const float* att1 = (const float*)d_in[4];
    const float* b1   = (const float*)d_in[5];
    const float* gam  = (const float*)d_in[6];
    const float* bet  = (const float*)d_in[7];
    const float* Wl2  = (const float*)d_in[8];
    const float* Wr2  = (const float*)d_in[9];
    const float* att2 = (const float*)d_in[10];
    const float* b2   = (const float*)d_in[11];
    const float* Wout = (const float*)d_in[12];
    const float* bout = (const float*)d_in[13];
    float* out = (float*)d_out;
    float* outAlpha = out + (size_t)NN * 3;
    int writeAlpha = (out_size >= NN * 3 + ET * 4);

    cudaFuncSetAttribute(k_gemm1, cudaFuncAttributeMaxDynamicSharedMemorySize, 196608);
    cudaFuncSetAttribute(k_gemm2, cudaFuncAttributeMaxDynamicSharedMemorySize, 98304);

    k_zero_cnt<<<256, 256>>>(ei);
    k_hist<<<2048, 256>>>(ei);
    k_scanA<<<NB, 256>>>();
    k_scanB<<<1, NB>>>();
    k_scanC<<<NB, 256>>>();
    k_scatter<<<2048, 256>>>(ei);
    k_gemm1<<<(NN + 127) / 128, 512, 196608>>>(x, Wl1, Wr1);
    k_score1_csr<<<(NN * 32 + 255) / 256, 256>>>(att1, outAlpha, writeAlpha);
    k_bnstat<<<1024, 128>>>(b1);
    k_bnfin<<<1, 128>>>(gam, bet, b1);
    k_gemm2<<<(NN + 127) / 128, 512, 98304>>>(Wl2, Wr2);
    k_score2_csr<<<(NN * 32 + 255) / 256, 256>>>(att2);
    k_final<<<(NN + 7) / 8, 256>>>(b2, Wout, bout, out);
}